// round 6
// baseline (speedup 1.0000x reference)
#include <cuda_runtime.h>
#include <math.h>

// Shapes (fixed): B=8, L=1024, D=512, H=8, dh=64
//
// Decomposition:
//   K1: Q,K,V = x @ {Wq,Wk,Wv}            (8192x512x512 fp32 SGEMM x3)
//   K2: R2[b,h,l,d] = Q[b,:,h,:] @ WeF     (WeF[:,j] = We[:,1023-j]) ; d = |l-s|
//   K3: flash attention, logits = 0.125 * (q_l . k_s) * R2[l,|l-s|]
//
// Derivation of the pad/reflect/reshape trick: s_rel[l,s] = qe[l, L-1-|l-s|].

static __device__ float g_Q[8192 * 512];
static __device__ float g_K[8192 * 512];
static __device__ float g_V[8192 * 512];
static __device__ float g_R2[67108864];   // [B*H][1024][1024] = 256 MB

// ---------------------------------------------------------------------------
// K1: C = x @ W,  M=8192, N=512, K=512.  blockIdx.z selects {Wq,Wk,Wv}.
// 128x128 tile, BK=16, 256 threads, 8x8 micro split as 4+4 rows/cols.
// ---------------------------------------------------------------------------
__global__ __launch_bounds__(256) void k_qkv_gemm(
    const float* __restrict__ x,
    const float* __restrict__ Wq,
    const float* __restrict__ Wk,
    const float* __restrict__ Wv)
{
    __shared__ float As[16][132];   // [k][m], padded (stride 132) for store conflicts
    __shared__ float Bs[16][128];   // [k][n]

    const float* __restrict__ W = (blockIdx.z == 0) ? Wq : (blockIdx.z == 1) ? Wk : Wv;
    float* __restrict__ C = (blockIdx.z == 0) ? g_Q : (blockIdx.z == 1) ? g_K : g_V;

    const int m0 = blockIdx.y * 128;
    const int n0 = blockIdx.x * 128;
    const int tid = threadIdx.x;
    const int ty = tid >> 4;
    const int tx = tid & 15;

    float acc[8][8];
#pragma unroll
    for (int i = 0; i < 8; i++)
#pragma unroll
        for (int j = 0; j < 8; j++) acc[i][j] = 0.f;

    for (int k0 = 0; k0 < 512; k0 += 16) {
#pragma unroll
        for (int r = 0; r < 8; r++) {
            int idx = tid + r * 256;
            int m = idx >> 4, k = idx & 15;
            As[k][m] = x[(size_t)(m0 + m) * 512 + (k0 + k)];
        }
#pragma unroll
        for (int r = 0; r < 8; r++) {
            int idx = tid + r * 256;
            int k = idx >> 7, n = idx & 127;
            Bs[k][n] = W[(size_t)(k0 + k) * 512 + (n0 + n)];
        }
        __syncthreads();
#pragma unroll
        for (int k = 0; k < 16; k++) {
            float a[8], b[8];
            *(float4*)&a[0] = *(const float4*)&As[k][ty * 4];
            *(float4*)&a[4] = *(const float4*)&As[k][64 + ty * 4];
            *(float4*)&b[0] = *(const float4*)&Bs[k][tx * 4];
            *(float4*)&b[4] = *(const float4*)&Bs[k][64 + tx * 4];
#pragma unroll
            for (int i = 0; i < 8; i++)
#pragma unroll
                for (int j = 0; j < 8; j++)
                    acc[i][j] = fmaf(a[i], b[j], acc[i][j]);
        }
        __syncthreads();
    }

#pragma unroll
    for (int i = 0; i < 8; i++) {
        int m = m0 + ((i < 4) ? (ty * 4 + i) : (64 + ty * 4 + (i - 4)));
#pragma unroll
        for (int jg = 0; jg < 2; jg++) {
            float4 v = make_float4(acc[i][jg * 4 + 0], acc[i][jg * 4 + 1],
                                   acc[i][jg * 4 + 2], acc[i][jg * 4 + 3]);
            *(float4*)&C[(size_t)m * 512 + n0 + jg * 64 + tx * 4] = v;
        }
    }
}

// ---------------------------------------------------------------------------
// K2: R2[bh] = Q_head[1024,64] @ WeF[64,1024]   (WeF[k][n] = We[k][1023-n])
// Same tiling as K1, K=64. blockIdx.z = bh in [0,64).
// ---------------------------------------------------------------------------
__global__ __launch_bounds__(256) void k_rel_gemm(const float* __restrict__ We)
{
    __shared__ float As[16][132];
    __shared__ float Bs[16][128];

    const int bh = blockIdx.z;
    const float* __restrict__ A = g_Q + (size_t)(bh >> 3) * 1024 * 512 + (size_t)(bh & 7) * 64;
    float* __restrict__ C = g_R2 + (size_t)bh * 1024 * 1024;

    const int m0 = blockIdx.y * 128;
    const int n0 = blockIdx.x * 128;
    const int tid = threadIdx.x;
    const int ty = tid >> 4;
    const int tx = tid & 15;

    float acc[8][8];
#pragma unroll
    for (int i = 0; i < 8; i++)
#pragma unroll
        for (int j = 0; j < 8; j++) acc[i][j] = 0.f;

    for (int k0 = 0; k0 < 64; k0 += 16) {
#pragma unroll
        for (int r = 0; r < 8; r++) {
            int idx = tid + r * 256;
            int m = idx >> 4, k = idx & 15;
            As[k][m] = A[(size_t)(m0 + m) * 512 + (k0 + k)];
        }
#pragma unroll
        for (int r = 0; r < 8; r++) {
            int idx = tid + r * 256;
            int k = idx >> 7, n = idx & 127;
            Bs[k][n] = We[(size_t)(k0 + k) * 1024 + (1023 - (n0 + n))];
        }
        __syncthreads();
#pragma unroll
        for (int k = 0; k < 16; k++) {
            float a[8], b[8];
            *(float4*)&a[0] = *(const float4*)&As[k][ty * 4];
            *(float4*)&a[4] = *(const float4*)&As[k][64 + ty * 4];
            *(float4*)&b[0] = *(const float4*)&Bs[k][tx * 4];
            *(float4*)&b[4] = *(const float4*)&Bs[k][64 + tx * 4];
#pragma unroll
            for (int i = 0; i < 8; i++)
#pragma unroll
                for (int j = 0; j < 8; j++)
                    acc[i][j] = fmaf(a[i], b[j], acc[i][j]);
        }
        __syncthreads();
    }

#pragma unroll
    for (int i = 0; i < 8; i++) {
        int m = m0 + ((i < 4) ? (ty * 4 + i) : (64 + ty * 4 + (i - 4)));
#pragma unroll
        for (int jg = 0; jg < 2; jg++) {
            float4 v = make_float4(acc[i][jg * 4 + 0], acc[i][jg * 4 + 1],
                                   acc[i][jg * 4 + 2], acc[i][jg * 4 + 3]);
            *(float4*)&C[(size_t)m * 1024 + n0 + jg * 64 + tx * 4] = v;
        }
    }
}

// ---------------------------------------------------------------------------
// K3: flash attention. Block = (b, h, 64 query rows). 256 threads, 4x4 micro.
// Dynamic smem: Qt/Kt transposed [d][l|s], Vs natural [s][d], Ps [l][s].
// ---------------------------------------------------------------------------
__global__ __launch_bounds__(256) void k_attn(float* __restrict__ out)
{
    extern __shared__ float sm[];
    float (*Qt)[68] = (float(*)[68])(sm);
    float (*Kt)[68] = (float(*)[68])(sm + 64 * 68);
    float (*Vs)[68] = (float(*)[68])(sm + 2 * 64 * 68);
    float (*Ps)[68] = (float(*)[68])(sm + 3 * 64 * 68);

    const int l0 = blockIdx.x * 64;
    const int h  = blockIdx.y;
    const int b  = blockIdx.z;
    const int tid = threadIdx.x;
    const int ty = tid >> 4;
    const int tx = tid & 15;

    const size_t headoff = (size_t)b * 1024 * 512 + (size_t)h * 64;
    const float* __restrict__ Qg = g_Q + headoff;
    const float* __restrict__ Kg = g_K + headoff;
    const float* __restrict__ Vg = g_V + headoff;
    const float* __restrict__ R  = g_R2 + (size_t)(b * 8 + h) * 1024 * 1024;

    // Load Q tile transposed: Qt[d][l_local]
    {
        int row = tid >> 2;            // l_local 0..63
        int g4  = (tid & 3) * 4;       // d base, i-step 16 (2-way STS conflicts)
        const float* src = Qg + (size_t)(l0 + row) * 512;
#pragma unroll
        for (int i = 0; i < 4; i++) {
            int d = g4 + i * 16;
            float4 v = *(const float4*)(src + d);
            Qt[d + 0][row] = v.x;
            Qt[d + 1][row] = v.y;
            Qt[d + 2][row] = v.z;
            Qt[d + 3][row] = v.w;
        }
    }

    float m_[4], r_[4], O[4][4];
#pragma unroll
    for (int i = 0; i < 4; i++) {
        m_[i] = -INFINITY;
        r_[i] = 0.f;
#pragma unroll
        for (int j = 0; j < 4; j++) O[i][j] = 0.f;
    }

    const float scale = 0.125f;

    for (int s0 = 0; s0 < 1024; s0 += 64) {
        __syncthreads();   // previous PV done (and Qt visible on first iter)
        {
            int row = tid >> 2;
            int g4  = (tid & 3) * 4;
            const float* ks = Kg + (size_t)(s0 + row) * 512;
            const float* vs = Vg + (size_t)(s0 + row) * 512;
#pragma unroll
            for (int i = 0; i < 4; i++) {
                int d = g4 + i * 16;
                float4 kv = *(const float4*)(ks + d);
                Kt[d + 0][row] = kv.x;
                Kt[d + 1][row] = kv.y;
                Kt[d + 2][row] = kv.z;
                Kt[d + 3][row] = kv.w;
                *(float4*)&Vs[row][d] = *(const float4*)(vs + d);
            }
        }
        __syncthreads();

        // S = Q @ K^T  (64x64, k=64), 4x4 fragment per thread
        float S[4][4];
#pragma unroll
        for (int i = 0; i < 4; i++)
#pragma unroll
            for (int j = 0; j < 4; j++) S[i][j] = 0.f;

#pragma unroll 16
        for (int d = 0; d < 64; d++) {
            float4 qa = *(const float4*)&Qt[d][ty * 4];
            float4 kb = *(const float4*)&Kt[d][tx * 4];
            float a_[4] = {qa.x, qa.y, qa.z, qa.w};
            float b_[4] = {kb.x, kb.y, kb.z, kb.w};
#pragma unroll
            for (int i = 0; i < 4; i++)
#pragma unroll
                for (int j = 0; j < 4; j++)
                    S[i][j] = fmaf(a_[i], b_[j], S[i][j]);
        }

        // logits = scale * S * R2[l, |l-s|]; online softmax; store P
#pragma unroll
        for (int i = 0; i < 4; i++) {
            const int l = l0 + ty * 4 + i;
            const float* Rrow = R + (size_t)l * 1024;
#pragma unroll
            for (int j = 0; j < 4; j++) {
                int s = s0 + tx * 4 + j;
                int dd = l - s;
                dd = (dd < 0) ? -dd : dd;
                S[i][j] = scale * S[i][j] * Rrow[dd];
            }
            float rm = fmaxf(fmaxf(S[i][0], S[i][1]), fmaxf(S[i][2], S[i][3]));
#pragma unroll
            for (int w = 1; w < 16; w <<= 1)
                rm = fmaxf(rm, __shfl_xor_sync(0xffffffffu, rm, w));
            float mn = fmaxf(m_[i], rm);
            float alpha = __expf(m_[i] - mn);   // exp(-inf)=0 on first tile
            float ssum = 0.f;
#pragma unroll
            for (int j = 0; j < 4; j++) {
                S[i][j] = __expf(S[i][j] - mn);
                ssum += S[i][j];
            }
#pragma unroll
            for (int w = 1; w < 16; w <<= 1)
                ssum += __shfl_xor_sync(0xffffffffu, ssum, w);
            r_[i] = r_[i] * alpha + ssum;
            m_[i] = mn;
#pragma unroll
            for (int j = 0; j < 4; j++) O[i][j] *= alpha;
            *(float4*)&Ps[ty * 4 + i][tx * 4] =
                make_float4(S[i][0], S[i][1], S[i][2], S[i][3]);
        }
        __syncthreads();

        // O += P @ V  (64x64 @ 64x64)
#pragma unroll 16
        for (int s = 0; s < 64; s++) {
            float4 vb = *(const float4*)&Vs[s][tx * 4];
            float v4[4] = {vb.x, vb.y, vb.z, vb.w};
            float p[4] = {Ps[ty * 4 + 0][s], Ps[ty * 4 + 1][s],
                          Ps[ty * 4 + 2][s], Ps[ty * 4 + 3][s]};
#pragma unroll
            for (int i = 0; i < 4; i++)
#pragma unroll
                for (int j = 0; j < 4; j++)
                    O[i][j] = fmaf(p[i], v4[j], O[i][j]);
        }
    }

    // Epilogue: out[b, l, h*64 + d] = O / r
#pragma unroll
    for (int i = 0; i < 4; i++) {
        float inv = 1.f / r_[i];
        float4 o = make_float4(O[i][0] * inv, O[i][1] * inv,
                               O[i][2] * inv, O[i][3] * inv);
        *(float4*)&out[(size_t)(b * 1024 + l0 + ty * 4 + i) * 512 + h * 64 + tx * 4] = o;
    }
}

// ---------------------------------------------------------------------------

extern "C" void kernel_launch(void* const* d_in, const int* in_sizes, int n_in,
                              void* d_out, int out_size)
{
    (void)in_sizes; (void)n_in; (void)out_size;
    const float* x  = (const float*)d_in[0];
    const float* Wq = (const float*)d_in[1];
    const float* Wk = (const float*)d_in[2];
    const float* Wv = (const float*)d_in[3];
    const float* We = (const float*)d_in[4];
    float* out = (float*)d_out;

    const int SMEM3 = 4 * 64 * 68 * (int)sizeof(float);   // 69632 B
    cudaFuncSetAttribute(k_attn, cudaFuncAttributeMaxDynamicSharedMemorySize, SMEM3);

    k_qkv_gemm<<<dim3(4, 64, 3), 256>>>(x, Wq, Wk, Wv);
    k_rel_gemm<<<dim3(8, 8, 64), 256>>>(We);
    k_attn<<<dim3(16, 8, 8), 256, SMEM3>>>(out);
}

// round 7
// speedup vs baseline: 1.1411x; 1.1411x over previous
#include <cuda_runtime.h>
#include <math.h>

// Shapes (fixed): B=8, L=1024, D=512, H=8, dh=64
//
//   K1: Q,K,V = x @ {Wq,Wk,Wv}            (8192x512x512 fp32 SGEMM x3)
//   K2: R2[b,h,l,d] = Q[b,:,h,:] @ WeF     (WeF[:,j] = We[:,1023-j]) ; d = |l-s|
//   K3: flash attention, logits = 0.125 * (q_l . k_s) * R2[l,|l-s|]

static __device__ float g_Q[8192 * 512];
static __device__ float g_K[8192 * 512];
static __device__ float g_V[8192 * 512];
static __device__ float g_R2[67108864];   // [B*H][1024][1024] = 256 MB

// ---------------------------------------------------------------------------
// K1: C = x @ W,  M=8192, N=512, K=512.  blockIdx.z selects {Wq,Wk,Wv}.
// 128x128 tile, BK=16, 256 threads, 8x8 micro (4+4 split).
// Double-buffered smem, one __syncthreads per k-tile, 2 CTAs/SM.
// ---------------------------------------------------------------------------
__global__ __launch_bounds__(256, 2) void k_qkv_gemm(
    const float* __restrict__ x,
    const float* __restrict__ Wq,
    const float* __restrict__ Wk,
    const float* __restrict__ Wv)
{
    __shared__ float As[2][16][132];   // [buf][k][m]
    __shared__ float Bs[2][16][128];   // [buf][k][n]

    const float* __restrict__ W = (blockIdx.z == 0) ? Wq : (blockIdx.z == 1) ? Wk : Wv;
    float* __restrict__ C = (blockIdx.z == 0) ? g_Q : (blockIdx.z == 1) ? g_K : g_V;

    const int m0 = blockIdx.y * 128;
    const int n0 = blockIdx.x * 128;
    const int tid = threadIdx.x;
    const int ty = tid >> 4;
    const int tx = tid & 15;

    float acc[8][8];
#pragma unroll
    for (int i = 0; i < 8; i++)
#pragma unroll
        for (int j = 0; j < 8; j++) acc[i][j] = 0.f;

    // ---- load tile 0 directly into buffer 0 ----
#pragma unroll
    for (int r = 0; r < 8; r++) {
        int idx = tid + r * 256;
        int m = idx >> 4, k = idx & 15;
        As[0][k][m] = x[(size_t)(m0 + m) * 512 + k];
    }
#pragma unroll
    for (int r = 0; r < 2; r++) {
        int idx = tid + r * 256;
        int k = idx >> 5, n4 = idx & 31;
        *(float4*)&Bs[0][k][n4 * 4] = *(const float4*)&W[(size_t)k * 512 + n0 + n4 * 4];
    }
    __syncthreads();

    const int KT = 32;
    for (int kt = 0; kt < KT; kt++) {
        const int cur = kt & 1, nxt = cur ^ 1;

        // prefetch next tile into registers
        float ra[8];
        float4 rb[2];
        if (kt + 1 < KT) {
            const int k0 = (kt + 1) * 16;
#pragma unroll
            for (int r = 0; r < 8; r++) {
                int idx = tid + r * 256;
                int m = idx >> 4, k = idx & 15;
                ra[r] = x[(size_t)(m0 + m) * 512 + k0 + k];
            }
#pragma unroll
            for (int r = 0; r < 2; r++) {
                int idx = tid + r * 256;
                int k = idx >> 5, n4 = idx & 31;
                rb[r] = *(const float4*)&W[(size_t)(k0 + k) * 512 + n0 + n4 * 4];
            }
        }

        // compute on current buffer
#pragma unroll
        for (int k = 0; k < 16; k++) {
            float a[8], b[8];
            *(float4*)&a[0] = *(const float4*)&As[cur][k][ty * 4];
            *(float4*)&a[4] = *(const float4*)&As[cur][k][64 + ty * 4];
            *(float4*)&b[0] = *(const float4*)&Bs[cur][k][tx * 4];
            *(float4*)&b[4] = *(const float4*)&Bs[cur][k][64 + tx * 4];
#pragma unroll
            for (int i = 0; i < 8; i++)
#pragma unroll
                for (int j = 0; j < 8; j++)
                    acc[i][j] = fmaf(a[i], b[j], acc[i][j]);
        }

        // stage next tile into the other buffer (not being read this iter)
        if (kt + 1 < KT) {
#pragma unroll
            for (int r = 0; r < 8; r++) {
                int idx = tid + r * 256;
                int m = idx >> 4, k = idx & 15;
                As[nxt][k][m] = ra[r];
            }
#pragma unroll
            for (int r = 0; r < 2; r++) {
                int idx = tid + r * 256;
                int k = idx >> 5, n4 = idx & 31;
                *(float4*)&Bs[nxt][k][n4 * 4] = rb[r];
            }
        }
        __syncthreads();
    }

#pragma unroll
    for (int i = 0; i < 8; i++) {
        int m = m0 + ((i < 4) ? (ty * 4 + i) : (64 + ty * 4 + (i - 4)));
#pragma unroll
        for (int jg = 0; jg < 2; jg++) {
            float4 v = make_float4(acc[i][jg * 4 + 0], acc[i][jg * 4 + 1],
                                   acc[i][jg * 4 + 2], acc[i][jg * 4 + 3]);
            *(float4*)&C[(size_t)m * 512 + n0 + jg * 64 + tx * 4] = v;
        }
    }
}

// ---------------------------------------------------------------------------
// K2: R2[bh] = Q_head[1024,64] @ WeF[64,1024]   (WeF[k][n] = We[k][1023-n])
// Same structure as K1, K=64 (4 k-tiles).
// ---------------------------------------------------------------------------
__global__ __launch_bounds__(256, 2) void k_rel_gemm(const float* __restrict__ We)
{
    __shared__ float As[2][16][132];
    __shared__ float Bs[2][16][128];

    const int bh = blockIdx.z;
    const float* __restrict__ A = g_Q + (size_t)(bh >> 3) * 1024 * 512 + (size_t)(bh & 7) * 64;
    float* __restrict__ C = g_R2 + (size_t)bh * 1024 * 1024;

    const int m0 = blockIdx.y * 128;
    const int n0 = blockIdx.x * 128;
    const int tid = threadIdx.x;
    const int ty = tid >> 4;
    const int tx = tid & 15;

    float acc[8][8];
#pragma unroll
    for (int i = 0; i < 8; i++)
#pragma unroll
        for (int j = 0; j < 8; j++) acc[i][j] = 0.f;

    // tile 0 -> buffer 0. B is column-flipped: Bs[k][n] = We[k][1023-(n0+n)]
#pragma unroll
    for (int r = 0; r < 8; r++) {
        int idx = tid + r * 256;
        int m = idx >> 4, k = idx & 15;
        As[0][k][m] = A[(size_t)(m0 + m) * 512 + k];
    }
#pragma unroll
    for (int r = 0; r < 2; r++) {
        int idx = tid + r * 256;
        int k = idx >> 5, n4 = idx & 31;
        float4 v = *(const float4*)&We[(size_t)k * 1024 + (1020 - n0 - n4 * 4)];
        Bs[0][k][n4 * 4 + 0] = v.w;
        Bs[0][k][n4 * 4 + 1] = v.z;
        Bs[0][k][n4 * 4 + 2] = v.y;
        Bs[0][k][n4 * 4 + 3] = v.x;
    }
    __syncthreads();

    const int KT = 4;
    for (int kt = 0; kt < KT; kt++) {
        const int cur = kt & 1, nxt = cur ^ 1;

        float ra[8];
        float4 rb[2];
        if (kt + 1 < KT) {
            const int k0 = (kt + 1) * 16;
#pragma unroll
            for (int r = 0; r < 8; r++) {
                int idx = tid + r * 256;
                int m = idx >> 4, k = idx & 15;
                ra[r] = A[(size_t)(m0 + m) * 512 + k0 + k];
            }
#pragma unroll
            for (int r = 0; r < 2; r++) {
                int idx = tid + r * 256;
                int k = idx >> 5, n4 = idx & 31;
                rb[r] = *(const float4*)&We[(size_t)(k0 + k) * 1024 + (1020 - n0 - n4 * 4)];
            }
        }

#pragma unroll
        for (int k = 0; k < 16; k++) {
            float a[8], b[8];
            *(float4*)&a[0] = *(const float4*)&As[cur][k][ty * 4];
            *(float4*)&a[4] = *(const float4*)&As[cur][k][64 + ty * 4];
            *(float4*)&b[0] = *(const float4*)&Bs[cur][k][tx * 4];
            *(float4*)&b[4] = *(const float4*)&Bs[cur][k][64 + tx * 4];
#pragma unroll
            for (int i = 0; i < 8; i++)
#pragma unroll
                for (int j = 0; j < 8; j++)
                    acc[i][j] = fmaf(a[i], b[j], acc[i][j]);
        }

        if (kt + 1 < KT) {
#pragma unroll
            for (int r = 0; r < 8; r++) {
                int idx = tid + r * 256;
                int m = idx >> 4, k = idx & 15;
                As[nxt][k][m] = ra[r];
            }
#pragma unroll
            for (int r = 0; r < 2; r++) {
                int idx = tid + r * 256;
                int k = idx >> 5, n4 = idx & 31;
                float4 v = rb[r];
                Bs[nxt][k][n4 * 4 + 0] = v.w;
                Bs[nxt][k][n4 * 4 + 1] = v.z;
                Bs[nxt][k][n4 * 4 + 2] = v.y;
                Bs[nxt][k][n4 * 4 + 3] = v.x;
            }
        }
        __syncthreads();
    }

#pragma unroll
    for (int i = 0; i < 8; i++) {
        int m = m0 + ((i < 4) ? (ty * 4 + i) : (64 + ty * 4 + (i - 4)));
#pragma unroll
        for (int jg = 0; jg < 2; jg++) {
            float4 v = make_float4(acc[i][jg * 4 + 0], acc[i][jg * 4 + 1],
                                   acc[i][jg * 4 + 2], acc[i][jg * 4 + 3]);
            *(float4*)&C[(size_t)m * 1024 + n0 + jg * 64 + tx * 4] = v;
        }
    }
}

// ---------------------------------------------------------------------------
// K3: flash attention. Block = (b, h, 128 query rows). 256 threads, 8x4 micro.
// smem: Qt[64][136] (transposed, 128 rows), Kt[64][68], Vs[64][68], Ps[128][68].
// ---------------------------------------------------------------------------
__global__ __launch_bounds__(256, 2) void k_attn(float* __restrict__ out)
{
    extern __shared__ float sm[];
    float (*Qt)[136] = (float(*)[136])(sm);                    //  64*136
    float (*Kt)[68]  = (float(*)[68])(sm + 64 * 136);          //  64*68
    float (*Vs)[68]  = (float(*)[68])(sm + 64 * 136 + 64 * 68);
    float (*Ps)[68]  = (float(*)[68])(sm + 64 * 136 + 2 * 64 * 68);

    const int l0 = blockIdx.x * 128;
    const int h  = blockIdx.y;
    const int b  = blockIdx.z;
    const int tid = threadIdx.x;
    const int ty = tid >> 4;    // 0..15 -> 8 query rows each
    const int tx = tid & 15;    // 0..15 -> 4 key cols each

    const size_t headoff = (size_t)b * 1024 * 512 + (size_t)h * 64;
    const float* __restrict__ Qg = g_Q + headoff;
    const float* __restrict__ Kg = g_K + headoff;
    const float* __restrict__ Vg = g_V + headoff;
    const float* __restrict__ R  = g_R2 + (size_t)(b * 8 + h) * 1024 * 1024;

    // Load Q tile transposed: Qt[d][row], 128 rows x 64 d. 32 floats/thread.
    {
        int row = tid >> 1;             // 0..127
        int db  = (tid & 1) * 32;       // 0 or 32
        const float* src = Qg + (size_t)(l0 + row) * 512 + db;
#pragma unroll
        for (int i = 0; i < 8; i++) {
            float4 v = *(const float4*)(src + i * 4);
            Qt[db + i * 4 + 0][row] = v.x;
            Qt[db + i * 4 + 1][row] = v.y;
            Qt[db + i * 4 + 2][row] = v.z;
            Qt[db + i * 4 + 3][row] = v.w;
        }
    }

    float m_[8], r_[8], O[8][4];
#pragma unroll
    for (int i = 0; i < 8; i++) {
        m_[i] = -INFINITY;
        r_[i] = 0.f;
#pragma unroll
        for (int j = 0; j < 4; j++) O[i][j] = 0.f;
    }

    const float scale = 0.125f;

    for (int s0 = 0; s0 < 1024; s0 += 64) {
        __syncthreads();   // prev PV done (Qt visible on first iter)
        {
            int row = tid >> 2;            // 0..63
            int db  = (tid & 3) * 16;      // 0,16,32,48
            const float* ks = Kg + (size_t)(s0 + row) * 512 + db;
            const float* vs = Vg + (size_t)(s0 + row) * 512 + db;
#pragma unroll
            for (int i = 0; i < 4; i++) {
                float4 kv = *(const float4*)(ks + i * 4);
                Kt[db + i * 4 + 0][row] = kv.x;
                Kt[db + i * 4 + 1][row] = kv.y;
                Kt[db + i * 4 + 2][row] = kv.z;
                Kt[db + i * 4 + 3][row] = kv.w;
                *(float4*)&Vs[row][db + i * 4] = *(const float4*)(vs + i * 4);
            }
        }
        __syncthreads();

        // S = Q @ K^T : 128x64, 8x4 fragment per thread
        float S[8][4];
#pragma unroll
        for (int i = 0; i < 8; i++)
#pragma unroll
            for (int j = 0; j < 4; j++) S[i][j] = 0.f;

#pragma unroll 8
        for (int d = 0; d < 64; d++) {
            float a[8], bb[4];
            *(float4*)&a[0] = *(const float4*)&Qt[d][ty * 8];
            *(float4*)&a[4] = *(const float4*)&Qt[d][ty * 8 + 4];
            *(float4*)&bb[0] = *(const float4*)&Kt[d][tx * 4];
#pragma unroll
            for (int i = 0; i < 8; i++)
#pragma unroll
                for (int j = 0; j < 4; j++)
                    S[i][j] = fmaf(a[i], bb[j], S[i][j]);
        }

        // logits = scale * S * R2[l, |l-s|]; online softmax; stage P
#pragma unroll
        for (int i = 0; i < 8; i++) {
            const int l = l0 + ty * 8 + i;
            const float* Rrow = R + (size_t)l * 1024;
#pragma unroll
            for (int j = 0; j < 4; j++) {
                int s = s0 + tx * 4 + j;
                int dd = l - s;
                dd = (dd < 0) ? -dd : dd;
                S[i][j] = scale * S[i][j] * Rrow[dd];
            }
            float rm = fmaxf(fmaxf(S[i][0], S[i][1]), fmaxf(S[i][2], S[i][3]));
#pragma unroll
            for (int w = 1; w < 16; w <<= 1)
                rm = fmaxf(rm, __shfl_xor_sync(0xffffffffu, rm, w));
            float mn = fmaxf(m_[i], rm);
            float alpha = __expf(m_[i] - mn);
            float ssum = 0.f;
#pragma unroll
            for (int j = 0; j < 4; j++) {
                S[i][j] = __expf(S[i][j] - mn);
                ssum += S[i][j];
            }
#pragma unroll
            for (int w = 1; w < 16; w <<= 1)
                ssum += __shfl_xor_sync(0xffffffffu, ssum, w);
            r_[i] = r_[i] * alpha + ssum;
            m_[i] = mn;
#pragma unroll
            for (int j = 0; j < 4; j++) O[i][j] *= alpha;
            *(float4*)&Ps[ty * 8 + i][tx * 4] =
                make_float4(S[i][0], S[i][1], S[i][2], S[i][3]);
        }
        __syncthreads();

        // O += P @ V  (128x64 @ 64x64)
#pragma unroll 8
        for (int s = 0; s < 64; s++) {
            float4 vb = *(const float4*)&Vs[s][tx * 4];
            float v4[4] = {vb.x, vb.y, vb.z, vb.w};
#pragma unroll
            for (int i = 0; i < 8; i++) {
                float p = Ps[ty * 8 + i][s];
#pragma unroll
                for (int j = 0; j < 4; j++)
                    O[i][j] = fmaf(p, v4[j], O[i][j]);
            }
        }
    }

    // Epilogue: out[b, l, h*64 + d] = O / r
#pragma unroll
    for (int i = 0; i < 8; i++) {
        float inv = 1.f / r_[i];
        float4 o = make_float4(O[i][0] * inv, O[i][1] * inv,
                               O[i][2] * inv, O[i][3] * inv);
        *(float4*)&out[(size_t)(b * 1024 + l0 + ty * 8 + i) * 512 + h * 64 + tx * 4] = o;
    }
}

// ---------------------------------------------------------------------------

extern "C" void kernel_launch(void* const* d_in, const int* in_sizes, int n_in,
                              void* d_out, int out_size)
{
    (void)in_sizes; (void)n_in; (void)out_size;
    const float* x  = (const float*)d_in[0];
    const float* Wq = (const float*)d_in[1];
    const float* Wk = (const float*)d_in[2];
    const float* Wv = (const float*)d_in[3];
    const float* We = (const float*)d_in[4];
    float* out = (float*)d_out;

    const int SMEM3 = (64 * 136 + 2 * 64 * 68 + 128 * 68) * (int)sizeof(float); // 104448
    cudaFuncSetAttribute(k_attn, cudaFuncAttributeMaxDynamicSharedMemorySize, SMEM3);

    k_qkv_gemm<<<dim3(4, 64, 3), 256>>>(x, Wq, Wk, Wv);
    k_rel_gemm<<<dim3(8, 8, 64), 256>>>(We);
    k_attn<<<dim3(8, 8, 8), 256, SMEM3>>>(out);
}

// round 9
// speedup vs baseline: 1.4867x; 1.3028x over previous
#include <cuda_runtime.h>
#include <cuda_bf16.h>
#include <math.h>
#include <cstdint>

// Shapes (fixed): B=8, L=1024, D=512, H=8, dh=64
//
//   K1: Q,K,V = x @ {Wq,Wk,Wv}   mma.sync bf16 hi/lo split (3 terms), fp32 accum
//   K2: R2[bh] = Q_head @ WeF^T  same path; Wet[n][k] = We[k][1023-n]
//   K3: flash attention (fp32 SIMT), logits = 0.125 * (q.k) * R2[l,|l-s|]

// ---------------- scratch (device globals; no allocations) ----------------
static __device__ float g_Q[8192 * 512];
static __device__ float g_K[8192 * 512];
static __device__ float g_V[8192 * 512];
static __device__ float g_R2[67108864];                 // [B*H][1024][1024]

static __device__ __nv_bfloat16 g_xh[8192 * 512], g_xl[8192 * 512];
static __device__ __nv_bfloat16 g_Wth[3 * 512 * 512], g_Wtl[3 * 512 * 512];   // Wt[z][n][k]
static __device__ __nv_bfloat16 g_Weth[1024 * 64], g_Wetl[1024 * 64];         // Wet[n][k]
static __device__ __nv_bfloat16 g_Qh[8192 * 512], g_Ql[8192 * 512];

// ---------------- PTX helpers (all baseline sm_80-era PTX, no 'a' features) --
__device__ __forceinline__ uint32_t smem_u32(const void* p) {
    uint32_t a;
    asm("{ .reg .u64 t; cvta.to.shared.u64 t, %1; cvt.u32.u64 %0, t; }" : "=r"(a) : "l"(p));
    return a;
}
__device__ __forceinline__ void ldm_x4(uint32_t a[4], uint32_t addr) {
    asm volatile("ldmatrix.sync.aligned.m8n8.x4.shared.b16 {%0,%1,%2,%3}, [%4];"
                 : "=r"(a[0]), "=r"(a[1]), "=r"(a[2]), "=r"(a[3]) : "r"(addr));
}
__device__ __forceinline__ void mma_bf16(float c[4], const uint32_t a[4],
                                         uint32_t b0, uint32_t b1) {
    asm volatile(
        "mma.sync.aligned.m16n8k16.row.col.f32.bf16.bf16.f32 "
        "{%0,%1,%2,%3}, {%4,%5,%6,%7}, {%8,%9}, {%0,%1,%2,%3};"
        : "+f"(c[0]), "+f"(c[1]), "+f"(c[2]), "+f"(c[3])
        : "r"(a[0]), "r"(a[1]), "r"(a[2]), "r"(a[3]), "r"(b0), "r"(b1));
}
__device__ __forceinline__ void cp_async16(uint32_t dst, const void* src) {
    asm volatile("cp.async.cg.shared.global [%0], [%1], 16;" :: "r"(dst), "l"(src) : "memory");
}
#define CP_COMMIT() asm volatile("cp.async.commit_group;" ::: "memory")
#define CP_WAIT1()  asm volatile("cp.async.wait_group 1;" ::: "memory")
#define CP_WAIT0()  asm volatile("cp.async.wait_group 0;" ::: "memory")

// ---------------- smem tile geometry ----------------
// Tile = 128 rows x 32 bf16, row stride 80 B (64 B data + 16 pad).
// Bank pattern (r*20)%32 makes ldmatrix 8-address groups conflict-free,
// and 80 % 16 == 0 keeps cp.async 16B stores aligned.
static constexpr int TROW = 80;       // bytes per row
static constexpr int TBYTES = 128 * TROW;   // 10240 per matrix
static constexpr int BUF = 4 * TBYTES;      // Ah, Al, Bh, Bl per buffer = 40960

// Issue one 128x32 tile (2 x 16B per thread, 256 threads).
__device__ __forceinline__ void issue_tile(uint32_t sdst, const __nv_bfloat16* __restrict__ g,
                                           long rstride, int tid) {
#pragma unroll
    for (int r = 0; r < 2; r++) {
        int idx = tid * 2 + r;               // 0..511
        int row = idx >> 2, c = idx & 3;
        cp_async16(sdst + row * TROW + c * 16, g + (long)row * rstride + c * 8);
    }
}

// Compute one BK=32 slab: acc += Ah*Bh + Al*Bh + Ah*Bl (3-term bf16 split).
__device__ __forceinline__ void compute32(uint32_t sAh, uint32_t sAl,
                                          uint32_t sBh, uint32_t sBl,
                                          float acc[2][8][4], int mw, int nw, int lid) {
#pragma unroll
    for (int ks = 0; ks < 2; ks++) {
        const int acol2 = (ks * 16 + ((lid >> 4) << 3)) * 2;
        const int arow  = mw + (lid & 15);
        uint32_t A0[4], A1[4], L0[4], L1[4];
        ldm_x4(A0, sAh + arow * TROW + acol2);
        ldm_x4(A1, sAh + (arow + 16) * TROW + acol2);
        ldm_x4(L0, sAl + arow * TROW + acol2);
        ldm_x4(L1, sAl + (arow + 16) * TROW + acol2);

        const int bcol2 = (ks * 16 + (((lid >> 3) & 1) << 3)) * 2;
        const int brow  = nw + (lid & 7) + (((lid >> 4) & 1) << 3);
        uint32_t Bx[4][4];
#pragma unroll
        for (int p = 0; p < 4; p++) ldm_x4(Bx[p], sBh + (brow + p * 16) * TROW + bcol2);
#pragma unroll
        for (int p = 0; p < 4; p++) {
            mma_bf16(acc[0][2 * p],     A0, Bx[p][0], Bx[p][1]);
            mma_bf16(acc[0][2 * p + 1], A0, Bx[p][2], Bx[p][3]);
            mma_bf16(acc[1][2 * p],     A1, Bx[p][0], Bx[p][1]);
            mma_bf16(acc[1][2 * p + 1], A1, Bx[p][2], Bx[p][3]);
            mma_bf16(acc[0][2 * p],     L0, Bx[p][0], Bx[p][1]);
            mma_bf16(acc[0][2 * p + 1], L0, Bx[p][2], Bx[p][3]);
            mma_bf16(acc[1][2 * p],     L1, Bx[p][0], Bx[p][1]);
            mma_bf16(acc[1][2 * p + 1], L1, Bx[p][2], Bx[p][3]);
        }
#pragma unroll
        for (int p = 0; p < 4; p++) ldm_x4(Bx[p], sBl + (brow + p * 16) * TROW + bcol2);
#pragma unroll
        for (int p = 0; p < 4; p++) {
            mma_bf16(acc[0][2 * p],     A0, Bx[p][0], Bx[p][1]);
            mma_bf16(acc[0][2 * p + 1], A0, Bx[p][2], Bx[p][3]);
            mma_bf16(acc[1][2 * p],     A1, Bx[p][0], Bx[p][1]);
            mma_bf16(acc[1][2 * p + 1], A1, Bx[p][2], Bx[p][3]);
        }
    }
}

// ---------------- conversion pre-kernels ----------------
__global__ void k_split_x(const float* __restrict__ src) {
    int i = (blockIdx.x * 256 + threadIdx.x) * 4;
    float4 v = *(const float4*)(src + i);
    __nv_bfloat16 h0 = __float2bfloat16(v.x), h1 = __float2bfloat16(v.y);
    __nv_bfloat16 h2 = __float2bfloat16(v.z), h3 = __float2bfloat16(v.w);
    *(__nv_bfloat162*)(g_xh + i)     = __nv_bfloat162(h0, h1);
    *(__nv_bfloat162*)(g_xh + i + 2) = __nv_bfloat162(h2, h3);
    *(__nv_bfloat162*)(g_xl + i)     = __nv_bfloat162(
        __float2bfloat16(v.x - __bfloat162float(h0)), __float2bfloat16(v.y - __bfloat162float(h1)));
    *(__nv_bfloat162*)(g_xl + i + 2) = __nv_bfloat162(
        __float2bfloat16(v.z - __bfloat162float(h2)), __float2bfloat16(v.w - __bfloat162float(h3)));
}

// Wt[z][n][k] = W_z[k][n], split hi/lo.
__global__ void k_wsplit(const float* __restrict__ Wq, const float* __restrict__ Wk,
                         const float* __restrict__ Wv) {
    __shared__ float t[32][33];
    const int z = blockIdx.z;
    const float* __restrict__ W = (z == 0) ? Wq : (z == 1) ? Wk : Wv;
    const int n0 = blockIdx.x * 32, k0 = blockIdx.y * 32;
    const int tx = threadIdx.x, ty = threadIdx.y;   // 32 x 8
#pragma unroll
    for (int i = 0; i < 32; i += 8)
        t[ty + i][tx] = W[(size_t)(k0 + ty + i) * 512 + n0 + tx];
    __syncthreads();
#pragma unroll
    for (int i = 0; i < 32; i += 8) {
        float v = t[tx][ty + i];
        __nv_bfloat16 h = __float2bfloat16(v);
        size_t o = (size_t)z * 262144 + (size_t)(n0 + ty + i) * 512 + k0 + tx;
        g_Wth[o] = h;
        g_Wtl[o] = __float2bfloat16(v - __bfloat162float(h));
    }
}

// Wet[n][k] = We[k][1023-n], split hi/lo.
__global__ void k_wesplit(const float* __restrict__ We) {
    int id = blockIdx.x * 256 + threadIdx.x;   // 65536
    int n = id >> 6, k = id & 63;
    float v = We[(size_t)k * 1024 + (1023 - n)];
    __nv_bfloat16 h = __float2bfloat16(v);
    g_Weth[id] = h;
    g_Wetl[id] = __float2bfloat16(v - __bfloat162float(h));
}

// ---------------------------------------------------------------------------
// K1: C = x @ W_z via mma.sync.  M=8192, N=512, K=512 (16 slabs of 32).
// Fused epilogue: z==0 also writes the bf16 hi/lo split of Q for K2.
// ---------------------------------------------------------------------------
__global__ __launch_bounds__(256, 2) void k_mma_qkv() {
    extern __shared__ __align__(16) char dsm[];
    const uint32_t sb0 = smem_u32(dsm);

    const int tid = threadIdx.x, lid = tid & 31, wid = tid >> 5;
    const int mw = (wid & 3) * 32, nw = (wid >> 2) * 64;
    const int n0 = blockIdx.x * 128, m0 = blockIdx.y * 128, z = blockIdx.z;

    const __nv_bfloat16* Ah = g_xh + (size_t)m0 * 512;
    const __nv_bfloat16* Al = g_xl + (size_t)m0 * 512;
    const __nv_bfloat16* Bh = g_Wth + (size_t)z * 262144 + (size_t)n0 * 512;
    const __nv_bfloat16* Bl = g_Wtl + (size_t)z * 262144 + (size_t)n0 * 512;

    float acc[2][8][4];
#pragma unroll
    for (int i = 0; i < 2; i++)
#pragma unroll
        for (int j = 0; j < 8; j++)
#pragma unroll
            for (int c = 0; c < 4; c++) acc[i][j][c] = 0.f;

    // prologue: tiles 0,1 in flight
#pragma unroll
    for (int t = 0; t < 2; t++) {
        const uint32_t sb = sb0 + t * BUF;
        issue_tile(sb + 0 * TBYTES, Ah + t * 32, 512, tid);
        issue_tile(sb + 1 * TBYTES, Al + t * 32, 512, tid);
        issue_tile(sb + 2 * TBYTES, Bh + t * 32, 512, tid);
        issue_tile(sb + 3 * TBYTES, Bl + t * 32, 512, tid);
        CP_COMMIT();
    }

    const int KT = 16;
    for (int kt = 0; kt < KT; kt++) {
        if (kt < KT - 1) CP_WAIT1(); else CP_WAIT0();
        __syncthreads();
        const uint32_t sb = sb0 + (kt & 1) * BUF;
        compute32(sb, sb + TBYTES, sb + 2 * TBYTES, sb + 3 * TBYTES, acc, mw, nw, lid);
        __syncthreads();
        if (kt + 2 < KT) {
            const int t = kt + 2;
            issue_tile(sb + 0 * TBYTES, Ah + t * 32, 512, tid);
            issue_tile(sb + 1 * TBYTES, Al + t * 32, 512, tid);
            issue_tile(sb + 2 * TBYTES, Bh + t * 32, 512, tid);
            issue_tile(sb + 3 * TBYTES, Bl + t * 32, 512, tid);
            CP_COMMIT();
        }
    }

    float* __restrict__ C = (z == 0) ? g_Q : (z == 1) ? g_K : g_V;
#pragma unroll
    for (int mt = 0; mt < 2; mt++)
#pragma unroll
        for (int nt = 0; nt < 8; nt++) {
            const float* c = acc[mt][nt];
            const int m = m0 + mw + mt * 16 + (lid >> 2);
            const int n = n0 + nw + (nt >> 1) * 16 + (nt & 1) * 8 + (lid & 3) * 2;
            *(float2*)&C[(size_t)m * 512 + n]       = make_float2(c[0], c[1]);
            *(float2*)&C[(size_t)(m + 8) * 512 + n] = make_float2(c[2], c[3]);
            if (z == 0) {
                __nv_bfloat16 h0 = __float2bfloat16(c[0]), h1 = __float2bfloat16(c[1]);
                __nv_bfloat16 h2 = __float2bfloat16(c[2]), h3 = __float2bfloat16(c[3]);
                *(__nv_bfloat162*)&g_Qh[(size_t)m * 512 + n] = __nv_bfloat162(h0, h1);
                *(__nv_bfloat162*)&g_Ql[(size_t)m * 512 + n] = __nv_bfloat162(
                    __float2bfloat16(c[0] - __bfloat162float(h0)),
                    __float2bfloat16(c[1] - __bfloat162float(h1)));
                *(__nv_bfloat162*)&g_Qh[(size_t)(m + 8) * 512 + n] = __nv_bfloat162(h2, h3);
                *(__nv_bfloat162*)&g_Ql[(size_t)(m + 8) * 512 + n] = __nv_bfloat162(
                    __float2bfloat16(c[2] - __bfloat162float(h2)),
                    __float2bfloat16(c[3] - __bfloat162float(h3)));
            }
        }
}

// ---------------------------------------------------------------------------
// K2: R2[bh] = Q_head @ Wet^T via mma.sync.  Per bh: M=1024, N=1024, K=64.
// ---------------------------------------------------------------------------
__global__ __launch_bounds__(256, 2) void k_mma_rel() {
    extern __shared__ __align__(16) char dsm[];
    const uint32_t sb0 = smem_u32(dsm);

    const int tid = threadIdx.x, lid = tid & 31, wid = tid >> 5;
    const int mw = (wid & 3) * 32, nw = (wid >> 2) * 64;
    const int n0 = blockIdx.x * 128, m0 = blockIdx.y * 128, bh = blockIdx.z;
    const int b = bh >> 3, h = bh & 7;

    const __nv_bfloat16* Ah = g_Qh + (size_t)(b * 1024 + m0) * 512 + h * 64;
    const __nv_bfloat16* Al = g_Ql + (size_t)(b * 1024 + m0) * 512 + h * 64;
    const __nv_bfloat16* Bh = g_Weth + (size_t)n0 * 64;
    const __nv_bfloat16* Bl = g_Wetl + (size_t)n0 * 64;

    float acc[2][8][4];
#pragma unroll
    for (int i = 0; i < 2; i++)
#pragma unroll
        for (int j = 0; j < 8; j++)
#pragma unroll
            for (int c = 0; c < 4; c++) acc[i][j][c] = 0.f;

#pragma unroll
    for (int t = 0; t < 2; t++) {
        const uint32_t sb = sb0 + t * BUF;
        issue_tile(sb + 0 * TBYTES, Ah + t * 32, 512, tid);
        issue_tile(sb + 1 * TBYTES, Al + t * 32, 512, tid);
        issue_tile(sb + 2 * TBYTES, Bh + t * 32, 64, tid);
        issue_tile(sb + 3 * TBYTES, Bl + t * 32, 64, tid);
        CP_COMMIT();
    }

#pragma unroll
    for (int kt = 0; kt < 2; kt++) {
        if (kt == 0) CP_WAIT1(); else CP_WAIT0();
        __syncthreads();
        const uint32_t sb = sb0 + kt * BUF;
        compute32(sb, sb + TBYTES, sb + 2 * TBYTES, sb + 3 * TBYTES, acc, mw, nw, lid);
        __syncthreads();
    }

    float* __restrict__ C = g_R2 + (size_t)bh * 1048576;
#pragma unroll
    for (int mt = 0; mt < 2; mt++)
#pragma unroll
        for (int nt = 0; nt < 8; nt++) {
            const float* c = acc[mt][nt];
            const int m = m0 + mw + mt * 16 + (lid >> 2);
            const int n = n0 + nw + (nt >> 1) * 16 + (nt & 1) * 8 + (lid & 3) * 2;
            *(float2*)&C[(size_t)m * 1024 + n]       = make_float2(c[0], c[1]);
            *(float2*)&C[(size_t)(m + 8) * 1024 + n] = make_float2(c[2], c[3]);
        }
}

// ---------------------------------------------------------------------------
// K3: flash attention (unchanged from passing round-7 kernel).
// ---------------------------------------------------------------------------
__global__ __launch_bounds__(256, 2) void k_attn(float* __restrict__ out)
{
    extern __shared__ float sm[];
    float (*Qt)[136] = (float(*)[136])(sm);
    float (*Kt)[68]  = (float(*)[68])(sm + 64 * 136);
    float (*Vs)[68]  = (float(*)[68])(sm + 64 * 136 + 64 * 68);
    float (*Ps)[68]  = (float(*)[68])(sm + 64 * 136 + 2 * 64 * 68);

    const int l0 = blockIdx.x * 128;
    const int h  = blockIdx.y;
    const int b  = blockIdx.z;
    const int tid = threadIdx.x;
    const int ty = tid >> 4;
    const int tx = tid & 15;

    const size_t headoff = (size_t)b * 1024 * 512 + (size_t)h * 64;
    const float* __restrict__ Qg = g_Q + headoff;
    const float* __restrict__ Kg = g_K + headoff;
    const float* __restrict__ Vg = g_V + headoff;
    const float* __restrict__ R  = g_R2 + (size_t)(b * 8 + h) * 1024 * 1024;

    {
        int row = tid >> 1;
        int db  = (tid & 1) * 32;
        const float* src = Qg + (size_t)(l0 + row) * 512 + db;
#pragma unroll
        for (int i = 0; i < 8; i++) {
            float4 v = *(const float4*)(src + i * 4);
            Qt[db + i * 4 + 0][row] = v.x;
            Qt[db + i * 4 + 1][row] = v.y;
            Qt[db + i * 4 + 2][row] = v.z;
            Qt[db + i * 4 + 3][row] = v.w;
        }
    }

    float m_[8], r_[8], O[8][4];
#pragma unroll
    for (int i = 0; i < 8; i++) {
        m_[i] = -INFINITY;
        r_[i] = 0.f;
#pragma unroll
        for (int j = 0; j < 4; j++) O[i][j] = 0.f;
    }

    const float scale = 0.125f;

    for (int s0 = 0; s0 < 1024; s0 += 64) {
        __syncthreads();
        {
            int row = tid >> 2;
            int db  = (tid & 3) * 16;
            const float* ks = Kg + (size_t)(s0 + row) * 512 + db;
            const float* vs = Vg + (size_t)(s0 + row) * 512 + db;
#pragma unroll
            for (int i = 0; i < 4; i++) {
                float4 kv = *(const float4*)(ks + i * 4);
                Kt[db + i * 4 + 0][row] = kv.x;
                Kt[db + i * 4 + 1][row] = kv.y;
                Kt[db + i * 4 + 2][row] = kv.z;
                Kt[db + i * 4 + 3][row] = kv.w;
                *(float4*)&Vs[row][db + i * 4] = *(const float4*)(vs + i * 4);
            }
        }
        __syncthreads();

        float S[8][4];
#pragma unroll
        for (int i = 0; i < 8; i++)
#pragma unroll
            for (int j = 0; j < 4; j++) S[i][j] = 0.f;

#pragma unroll 8
        for (int d = 0; d < 64; d++) {
            float a[8], bb[4];
            *(float4*)&a[0] = *(const float4*)&Qt[d][ty * 8];
            *(float4*)&a[4] = *(const float4*)&Qt[d][ty * 8 + 4];
            *(float4*)&bb[0] = *(const float4*)&Kt[d][tx * 4];
#pragma unroll
            for (int i = 0; i < 8; i++)
#pragma unroll
                for (int j = 0; j < 4; j++)
                    S[i][j] = fmaf(a[i], bb[j], S[i][j]);
        }

#pragma unroll
        for (int i = 0; i < 8; i++) {
            const int l = l0 + ty * 8 + i;
            const float* Rrow = R + (size_t)l * 1024;
#pragma unroll
            for (int j = 0; j < 4; j++) {
                int s = s0 + tx * 4 + j;
                int dd = l - s;
                dd = (dd < 0) ? -dd : dd;
                S[i][j] = scale * S[i][j] * Rrow[dd];
            }
            float rm = fmaxf(fmaxf(S[i][0], S[i][1]), fmaxf(S[i][2], S[i][3]));
#pragma unroll
            for (int w = 1; w < 16; w <<= 1)
                rm = fmaxf(rm, __shfl_xor_sync(0xffffffffu, rm, w));
            float mn = fmaxf(m_[i], rm);
            float alpha = __expf(m_[i] - mn);
            float ssum = 0.f;
#pragma unroll
            for (int j = 0; j < 4; j++) {
                S[i][j] = __expf(S[i][j] - mn);
                ssum += S[i][j];
            }
#pragma unroll
            for (int w = 1; w < 16; w <<= 1)
                ssum += __shfl_xor_sync(0xffffffffu, ssum, w);
            r_[i] = r_[i] * alpha + ssum;
            m_[i] = mn;
#pragma unroll
            for (int j = 0; j < 4; j++) O[i][j] *= alpha;
            *(float4*)&Ps[ty * 8 + i][tx * 4] =
                make_float4(S[i][0], S[i][1], S[i][2], S[i][3]);
        }
        __syncthreads();

#pragma unroll 8
        for (int s = 0; s < 64; s++) {
            float4 vb = *(const float4*)&Vs[s][tx * 4];
            float v4[4] = {vb.x, vb.y, vb.z, vb.w};
#pragma unroll
            for (int i = 0; i < 8; i++) {
                float p = Ps[ty * 8 + i][s];
#pragma unroll
                for (int j = 0; j < 4; j++)
                    O[i][j] = fmaf(p, v4[j], O[i][j]);
            }
        }
    }

#pragma unroll
    for (int i = 0; i < 8; i++) {
        float inv = 1.f / r_[i];
        float4 o = make_float4(O[i][0] * inv, O[i][1] * inv,
                               O[i][2] * inv, O[i][3] * inv);
        *(float4*)&out[(size_t)(b * 1024 + l0 + ty * 8 + i) * 512 + h * 64 + tx * 4] = o;
    }
}

// ---------------------------------------------------------------------------

extern "C" void kernel_launch(void* const* d_in, const int* in_sizes, int n_in,
                              void* d_out, int out_size)
{
    (void)in_sizes; (void)n_in; (void)out_size;
    const float* x  = (const float*)d_in[0];
    const float* Wq = (const float*)d_in[1];
    const float* Wk = (const float*)d_in[2];
    const float* Wv = (const float*)d_in[3];
    const float* We = (const float*)d_in[4];
    float* out = (float*)d_out;

    const int SMEM_MMA = 2 * BUF;   // 81920
    const int SMEM3 = (64 * 136 + 2 * 64 * 68 + 128 * 68) * (int)sizeof(float); // 104448
    cudaFuncSetAttribute(k_mma_qkv, cudaFuncAttributeMaxDynamicSharedMemorySize, SMEM_MMA);
    cudaFuncSetAttribute(k_mma_rel, cudaFuncAttributeMaxDynamicSharedMemorySize, SMEM_MMA);
    cudaFuncSetAttribute(k_attn, cudaFuncAttributeMaxDynamicSharedMemorySize, SMEM3);

    k_split_x<<<4096, 256>>>(x);
    k_wsplit<<<dim3(16, 16, 3), dim3(32, 8)>>>(Wq, Wk, Wv);
    k_wesplit<<<256, 256>>>(We);
    k_mma_qkv<<<dim3(4, 64, 3), 256, SMEM_MMA>>>();
    k_mma_rel<<<dim3(8, 8, 64), 256, SMEM_MMA>>>();
    k_attn<<<dim3(8, 8, 8), 256, SMEM3>>>(out);
}

// round 10
// speedup vs baseline: 2.4328x; 1.6364x over previous
#include <cuda_runtime.h>
#include <cuda_bf16.h>
#include <math.h>
#include <cstdint>

// Shapes (fixed): B=8, L=1024, D=512, H=8, dh=64
//
//   K1: Q,K,V = x @ {Wq,Wk,Wv}   mma.sync bf16 hi/lo split (3 terms), fp32 accum.
//       Epilogue writes ONLY bf16 hi/lo splits of Q, K, V (no fp32 copies).
//   K2: R2[bh] = Q_head @ WeF^T  same path; Wet[n][k] = We[k][1023-n]
//   K3: flash attention, fully tensorized (mma.sync), fp32 softmax,
//       logits = 0.125 * (q.k) * R2[l,|l-s|]

// ---------------- scratch (device globals; no allocations) ----------------
static __device__ float g_R2[67108864];                 // [B*H][1024][1024]

static __device__ __nv_bfloat16 g_xh[8192 * 512], g_xl[8192 * 512];
static __device__ __nv_bfloat16 g_Wth[3 * 512 * 512], g_Wtl[3 * 512 * 512];   // Wt[z][n][k]
static __device__ __nv_bfloat16 g_Weth[1024 * 64], g_Wetl[1024 * 64];         // Wet[n][k]
static __device__ __nv_bfloat16 g_Qh[8192 * 512], g_Ql[8192 * 512];
static __device__ __nv_bfloat16 g_Kh[8192 * 512], g_Kl[8192 * 512];
static __device__ __nv_bfloat16 g_Vh[8192 * 512], g_Vl[8192 * 512];

// ---------------- PTX helpers (baseline sm_80-era PTX only) ----------------
__device__ __forceinline__ uint32_t smem_u32(const void* p) {
    uint32_t a;
    asm("{ .reg .u64 t; cvta.to.shared.u64 t, %1; cvt.u32.u64 %0, t; }" : "=r"(a) : "l"(p));
    return a;
}
__device__ __forceinline__ void ldm_x4(uint32_t a[4], uint32_t addr) {
    asm volatile("ldmatrix.sync.aligned.m8n8.x4.shared.b16 {%0,%1,%2,%3}, [%4];"
                 : "=r"(a[0]), "=r"(a[1]), "=r"(a[2]), "=r"(a[3]) : "r"(addr));
}
__device__ __forceinline__ void ldm_x4_t(uint32_t a[4], uint32_t addr) {
    asm volatile("ldmatrix.sync.aligned.m8n8.x4.trans.shared.b16 {%0,%1,%2,%3}, [%4];"
                 : "=r"(a[0]), "=r"(a[1]), "=r"(a[2]), "=r"(a[3]) : "r"(addr));
}
__device__ __forceinline__ void mma_bf16(float c[4], const uint32_t a[4],
                                         uint32_t b0, uint32_t b1) {
    asm volatile(
        "mma.sync.aligned.m16n8k16.row.col.f32.bf16.bf16.f32 "
        "{%0,%1,%2,%3}, {%4,%5,%6,%7}, {%8,%9}, {%0,%1,%2,%3};"
        : "+f"(c[0]), "+f"(c[1]), "+f"(c[2]), "+f"(c[3])
        : "r"(a[0]), "r"(a[1]), "r"(a[2]), "r"(a[3]), "r"(b0), "r"(b1));
}
__device__ __forceinline__ void cp_async16(uint32_t dst, const void* src) {
    asm volatile("cp.async.cg.shared.global [%0], [%1], 16;" :: "r"(dst), "l"(src) : "memory");
}
#define CP_COMMIT() asm volatile("cp.async.commit_group;" ::: "memory")
#define CP_WAIT0()  asm volatile("cp.async.wait_group 0;" ::: "memory")
#define CP_WAIT1()  asm volatile("cp.async.wait_group 1;" ::: "memory")
#define CP_WAIT2()  asm volatile("cp.async.wait_group 2;" ::: "memory")

__device__ __forceinline__ uint32_t pack_bf16(float x, float y) {
    __nv_bfloat162 t(__float2bfloat16(x), __float2bfloat16(y));
    return *(uint32_t*)&t;
}
__device__ __forceinline__ float bhi(float v) {
    return __bfloat162float(__float2bfloat16(v));
}

// ---------------- K1/K2 smem tile geometry (128 x 32 bf16, stride 80 B) -----
static constexpr int TROW = 80;
static constexpr int TBYTES = 128 * TROW;   // 10240
static constexpr int BUF = 4 * TBYTES;      // 40960

__device__ __forceinline__ void issue_tile(uint32_t sdst, const __nv_bfloat16* __restrict__ g,
                                           long rstride, int tid) {
#pragma unroll
    for (int r = 0; r < 2; r++) {
        int idx = tid * 2 + r;
        int row = idx >> 2, c = idx & 3;
        cp_async16(sdst + row * TROW + c * 16, g + (long)row * rstride + c * 8);
    }
}

__device__ __forceinline__ void compute32(uint32_t sAh, uint32_t sAl,
                                          uint32_t sBh, uint32_t sBl,
                                          float acc[2][8][4], int mw, int nw, int lid) {
#pragma unroll
    for (int ks = 0; ks < 2; ks++) {
        const int acol2 = (ks * 16 + ((lid >> 4) << 3)) * 2;
        const int arow  = mw + (lid & 15);
        uint32_t A0[4], A1[4], L0[4], L1[4];
        ldm_x4(A0, sAh + arow * TROW + acol2);
        ldm_x4(A1, sAh + (arow + 16) * TROW + acol2);
        ldm_x4(L0, sAl + arow * TROW + acol2);
        ldm_x4(L1, sAl + (arow + 16) * TROW + acol2);

        const int bcol2 = (ks * 16 + (((lid >> 3) & 1) << 3)) * 2;
        const int brow  = nw + (lid & 7) + (((lid >> 4) & 1) << 3);
        uint32_t Bx[4][4];
#pragma unroll
        for (int p = 0; p < 4; p++) ldm_x4(Bx[p], sBh + (brow + p * 16) * TROW + bcol2);
#pragma unroll
        for (int p = 0; p < 4; p++) {
            mma_bf16(acc[0][2 * p],     A0, Bx[p][0], Bx[p][1]);
            mma_bf16(acc[0][2 * p + 1], A0, Bx[p][2], Bx[p][3]);
            mma_bf16(acc[1][2 * p],     A1, Bx[p][0], Bx[p][1]);
            mma_bf16(acc[1][2 * p + 1], A1, Bx[p][2], Bx[p][3]);
            mma_bf16(acc[0][2 * p],     L0, Bx[p][0], Bx[p][1]);
            mma_bf16(acc[0][2 * p + 1], L0, Bx[p][2], Bx[p][3]);
            mma_bf16(acc[1][2 * p],     L1, Bx[p][0], Bx[p][1]);
            mma_bf16(acc[1][2 * p + 1], L1, Bx[p][2], Bx[p][3]);
        }
#pragma unroll
        for (int p = 0; p < 4; p++) ldm_x4(Bx[p], sBl + (brow + p * 16) * TROW + bcol2);
#pragma unroll
        for (int p = 0; p < 4; p++) {
            mma_bf16(acc[0][2 * p],     A0, Bx[p][0], Bx[p][1]);
            mma_bf16(acc[0][2 * p + 1], A0, Bx[p][2], Bx[p][3]);
            mma_bf16(acc[1][2 * p],     A1, Bx[p][0], Bx[p][1]);
            mma_bf16(acc[1][2 * p + 1], A1, Bx[p][2], Bx[p][3]);
        }
    }
}

// ---------------- conversion pre-kernels ----------------
__global__ void k_split_x(const float* __restrict__ src) {
    int i = (blockIdx.x * 256 + threadIdx.x) * 4;
    float4 v = *(const float4*)(src + i);
    __nv_bfloat16 h0 = __float2bfloat16(v.x), h1 = __float2bfloat16(v.y);
    __nv_bfloat16 h2 = __float2bfloat16(v.z), h3 = __float2bfloat16(v.w);
    *(__nv_bfloat162*)(g_xh + i)     = __nv_bfloat162(h0, h1);
    *(__nv_bfloat162*)(g_xh + i + 2) = __nv_bfloat162(h2, h3);
    *(__nv_bfloat162*)(g_xl + i)     = __nv_bfloat162(
        __float2bfloat16(v.x - __bfloat162float(h0)), __float2bfloat16(v.y - __bfloat162float(h1)));
    *(__nv_bfloat162*)(g_xl + i + 2) = __nv_bfloat162(
        __float2bfloat16(v.z - __bfloat162float(h2)), __float2bfloat16(v.w - __bfloat162float(h3)));
}

__global__ void k_wsplit(const float* __restrict__ Wq, const float* __restrict__ Wk,
                         const float* __restrict__ Wv) {
    __shared__ float t[32][33];
    const int z = blockIdx.z;
    const float* __restrict__ W = (z == 0) ? Wq : (z == 1) ? Wk : Wv;
    const int n0 = blockIdx.x * 32, k0 = blockIdx.y * 32;
    const int tx = threadIdx.x, ty = threadIdx.y;
#pragma unroll
    for (int i = 0; i < 32; i += 8)
        t[ty + i][tx] = W[(size_t)(k0 + ty + i) * 512 + n0 + tx];
    __syncthreads();
#pragma unroll
    for (int i = 0; i < 32; i += 8) {
        float v = t[tx][ty + i];
        __nv_bfloat16 h = __float2bfloat16(v);
        size_t o = (size_t)z * 262144 + (size_t)(n0 + ty + i) * 512 + k0 + tx;
        g_Wth[o] = h;
        g_Wtl[o] = __float2bfloat16(v - __bfloat162float(h));
    }
}

__global__ void k_wesplit(const float* __restrict__ We) {
    int id = blockIdx.x * 256 + threadIdx.x;
    int n = id >> 6, k = id & 63;
    float v = We[(size_t)k * 1024 + (1023 - n)];
    __nv_bfloat16 h = __float2bfloat16(v);
    g_Weth[id] = h;
    g_Wetl[id] = __float2bfloat16(v - __bfloat162float(h));
}

// ---------------------------------------------------------------------------
// K1: {Q,K,V} = x @ W_z via mma.sync. Epilogue: bf16 hi/lo splits only.
// ---------------------------------------------------------------------------
__global__ __launch_bounds__(256, 2) void k_mma_qkv() {
    extern __shared__ __align__(16) char dsm[];
    const uint32_t sb0 = smem_u32(dsm);

    const int tid = threadIdx.x, lid = tid & 31, wid = tid >> 5;
    const int mw = (wid & 3) * 32, nw = (wid >> 2) * 64;
    const int n0 = blockIdx.x * 128, m0 = blockIdx.y * 128, z = blockIdx.z;

    const __nv_bfloat16* Ah = g_xh + (size_t)m0 * 512;
    const __nv_bfloat16* Al = g_xl + (size_t)m0 * 512;
    const __nv_bfloat16* Bh = g_Wth + (size_t)z * 262144 + (size_t)n0 * 512;
    const __nv_bfloat16* Bl = g_Wtl + (size_t)z * 262144 + (size_t)n0 * 512;

    float acc[2][8][4];
#pragma unroll
    for (int i = 0; i < 2; i++)
#pragma unroll
        for (int j = 0; j < 8; j++)
#pragma unroll
            for (int c = 0; c < 4; c++) acc[i][j][c] = 0.f;

#pragma unroll
    for (int t = 0; t < 2; t++) {
        const uint32_t sb = sb0 + t * BUF;
        issue_tile(sb + 0 * TBYTES, Ah + t * 32, 512, tid);
        issue_tile(sb + 1 * TBYTES, Al + t * 32, 512, tid);
        issue_tile(sb + 2 * TBYTES, Bh + t * 32, 512, tid);
        issue_tile(sb + 3 * TBYTES, Bl + t * 32, 512, tid);
        CP_COMMIT();
    }

    const int KT = 16;
    for (int kt = 0; kt < KT; kt++) {
        if (kt < KT - 1) CP_WAIT1(); else CP_WAIT0();
        __syncthreads();
        const uint32_t sb = sb0 + (kt & 1) * BUF;
        compute32(sb, sb + TBYTES, sb + 2 * TBYTES, sb + 3 * TBYTES, acc, mw, nw, lid);
        __syncthreads();
        if (kt + 2 < KT) {
            const int t = kt + 2;
            issue_tile(sb + 0 * TBYTES, Ah + t * 32, 512, tid);
            issue_tile(sb + 1 * TBYTES, Al + t * 32, 512, tid);
            issue_tile(sb + 2 * TBYTES, Bh + t * 32, 512, tid);
            issue_tile(sb + 3 * TBYTES, Bl + t * 32, 512, tid);
            CP_COMMIT();
        }
    }

    __nv_bfloat16* __restrict__ Ho = (z == 0) ? g_Qh : (z == 1) ? g_Kh : g_Vh;
    __nv_bfloat16* __restrict__ Lo = (z == 0) ? g_Ql : (z == 1) ? g_Kl : g_Vl;
#pragma unroll
    for (int mt = 0; mt < 2; mt++)
#pragma unroll
        for (int nt = 0; nt < 8; nt++) {
            const float* c = acc[mt][nt];
            const int m = m0 + mw + mt * 16 + (lid >> 2);
            const int n = n0 + nw + (nt >> 1) * 16 + (nt & 1) * 8 + (lid & 3) * 2;
            float h0 = bhi(c[0]), h1 = bhi(c[1]), h2 = bhi(c[2]), h3 = bhi(c[3]);
            *(uint32_t*)&Ho[(size_t)m * 512 + n]       = pack_bf16(h0, h1);
            *(uint32_t*)&Lo[(size_t)m * 512 + n]       = pack_bf16(c[0] - h0, c[1] - h1);
            *(uint32_t*)&Ho[(size_t)(m + 8) * 512 + n] = pack_bf16(h2, h3);
            *(uint32_t*)&Lo[(size_t)(m + 8) * 512 + n] = pack_bf16(c[2] - h2, c[3] - h3);
        }
}

// ---------------------------------------------------------------------------
// K2: R2[bh] = Q_head @ Wet^T via mma.sync.  Per bh: M=1024, N=1024, K=64.
// ---------------------------------------------------------------------------
__global__ __launch_bounds__(256, 2) void k_mma_rel() {
    extern __shared__ __align__(16) char dsm[];
    const uint32_t sb0 = smem_u32(dsm);

    const int tid = threadIdx.x, lid = tid & 31, wid = tid >> 5;
    const int mw = (wid & 3) * 32, nw = (wid >> 2) * 64;
    const int n0 = blockIdx.x * 128, m0 = blockIdx.y * 128, bh = blockIdx.z;
    const int b = bh >> 3, h = bh & 7;

    const __nv_bfloat16* Ah = g_Qh + (size_t)(b * 1024 + m0) * 512 + h * 64;
    const __nv_bfloat16* Al = g_Ql + (size_t)(b * 1024 + m0) * 512 + h * 64;
    const __nv_bfloat16* Bh = g_Weth + (size_t)n0 * 64;
    const __nv_bfloat16* Bl = g_Wetl + (size_t)n0 * 64;

    float acc[2][8][4];
#pragma unroll
    for (int i = 0; i < 2; i++)
#pragma unroll
        for (int j = 0; j < 8; j++)
#pragma unroll
            for (int c = 0; c < 4; c++) acc[i][j][c] = 0.f;

#pragma unroll
    for (int t = 0; t < 2; t++) {
        const uint32_t sb = sb0 + t * BUF;
        issue_tile(sb + 0 * TBYTES, Ah + t * 32, 512, tid);
        issue_tile(sb + 1 * TBYTES, Al + t * 32, 512, tid);
        issue_tile(sb + 2 * TBYTES, Bh + t * 32, 64, tid);
        issue_tile(sb + 3 * TBYTES, Bl + t * 32, 64, tid);
        CP_COMMIT();
    }

#pragma unroll
    for (int kt = 0; kt < 2; kt++) {
        if (kt == 0) CP_WAIT1(); else CP_WAIT0();
        __syncthreads();
        const uint32_t sb = sb0 + kt * BUF;
        compute32(sb, sb + TBYTES, sb + 2 * TBYTES, sb + 3 * TBYTES, acc, mw, nw, lid);
        __syncthreads();
    }

    float* __restrict__ C = g_R2 + (size_t)bh * 1048576;
#pragma unroll
    for (int mt = 0; mt < 2; mt++)
#pragma unroll
        for (int nt = 0; nt < 8; nt++) {
            const float* c = acc[mt][nt];
            const int m = m0 + mw + mt * 16 + (lid >> 2);
            const int n = n0 + nw + (nt >> 1) * 16 + (nt & 1) * 8 + (lid & 3) * 2;
            *(float2*)&C[(size_t)m * 1024 + n]       = make_float2(c[0], c[1]);
            *(float2*)&C[(size_t)(m + 8) * 1024 + n] = make_float2(c[2], c[3]);
        }
}

// ---------------------------------------------------------------------------
// K3: tensorized flash attention.
// CTA = (l-tile 128, h, b); 8 warps, each m16 query rows x full n.
// smem: Qh/Ql staged once (128x64, stride 144), then 2 KV buffers
//       (Kh,Kl,Vh,Vl each 64x64, stride 144).
// ---------------------------------------------------------------------------
static constexpr int SROW = 144;                    // 128B data + 16 pad
static constexpr int QMAT = 128 * SROW;             // 18432
static constexpr int KVMAT = 64 * SROW;             // 9216
static constexpr int KVBUF = 4 * KVMAT;             // 36864
static constexpr int SMEM_ATT = 2 * QMAT + 2 * KVBUF;   // 110592

__device__ __forceinline__ void issue_q128(uint32_t s, const __nv_bfloat16* __restrict__ g, int tid) {
#pragma unroll
    for (int i = 0; i < 4; i++) {
        int idx = tid * 4 + i;                 // 0..1023
        int row = idx >> 3, c = idx & 7;
        cp_async16(s + row * SROW + c * 16, g + (size_t)row * 512 + c * 8);
    }
}
__device__ __forceinline__ void issue_kv64(uint32_t s, const __nv_bfloat16* __restrict__ g, int tid) {
#pragma unroll
    for (int i = 0; i < 2; i++) {
        int idx = tid * 2 + i;                 // 0..511
        int row = idx >> 3, c = idx & 7;
        cp_async16(s + row * SROW + c * 16, g + (size_t)row * 512 + c * 8);
    }
}

__global__ __launch_bounds__(256) void k_attn_mma(float* __restrict__ out) {
    extern __shared__ __align__(16) char dsm[];
    const uint32_t sb = smem_u32(dsm);
    const uint32_t sQh = sb, sQl = sb + QMAT;
    const uint32_t sBuf = sb + 2 * QMAT;

    const int tid = threadIdx.x, lid = tid & 31, wid = tid >> 5;
    const int l0 = blockIdx.x * 128, h = blockIdx.y, b = blockIdx.z;

    const size_t rowoff = (size_t)(b * 1024) * 512 + h * 64;
    const __nv_bfloat16* Qhg = g_Qh + rowoff + (size_t)l0 * 512;
    const __nv_bfloat16* Qlg = g_Ql + rowoff + (size_t)l0 * 512;
    const __nv_bfloat16* Khg = g_Kh + rowoff;
    const __nv_bfloat16* Klg = g_Kl + rowoff;
    const __nv_bfloat16* Vhg = g_Vh + rowoff;
    const __nv_bfloat16* Vlg = g_Vl + rowoff;
    const float* __restrict__ R = g_R2 + (size_t)(b * 8 + h) * 1048576;

    // stage Q + first two KV tiles
    issue_q128(sQh, Qhg, tid);
    issue_q128(sQl, Qlg, tid);
    CP_COMMIT();
#pragma unroll
    for (int t = 0; t < 2; t++) {
        const uint32_t Bt = sBuf + t * KVBUF;
        issue_kv64(Bt,             Khg + (size_t)t * 64 * 512, tid);
        issue_kv64(Bt + KVMAT,     Klg + (size_t)t * 64 * 512, tid);
        issue_kv64(Bt + 2 * KVMAT, Vhg + (size_t)t * 64 * 512, tid);
        issue_kv64(Bt + 3 * KVMAT, Vlg + (size_t)t * 64 * 512, tid);
        CP_COMMIT();
    }
    CP_WAIT2();
    __syncthreads();

    // Q fragments, registers, for all 4 k-steps (hi and lo)
    uint32_t QH[4][4], QL[4][4];
    {
        const int aoff = (16 * wid + (lid & 15)) * SROW;
#pragma unroll
        for (int ks = 0; ks < 4; ks++) {
            const int c2 = (ks * 16 + ((lid >> 4) << 3)) * 2;
            ldm_x4(QH[ks], sQh + aoff + c2);
            ldm_x4(QL[ks], sQl + aoff + c2);
        }
    }

    float O[8][4];
#pragma unroll
    for (int t = 0; t < 8; t++)
#pragma unroll
        for (int j = 0; j < 4; j++) O[t][j] = 0.f;
    float m0f = -INFINITY, m1f = -INFINITY, r0f = 0.f, r1f = 0.f;

    const int r0 = lid >> 2, c2i = (lid & 3) * 2;
    const int lA = l0 + 16 * wid + r0, lB = lA + 8;
    const float* RA = R + (size_t)lA * 1024;
    const float* RB = R + (size_t)lB * 1024;

    for (int kt = 0; kt < 16; kt++) {
        if (kt < 15) CP_WAIT1(); else CP_WAIT0();
        __syncthreads();
        const uint32_t Bt = sBuf + (kt & 1) * KVBUF;
        const uint32_t bKh = Bt, bKl = Bt + KVMAT, bVh = Bt + 2 * KVMAT, bVl = Bt + 3 * KVMAT;

        // ---- S = Q @ K^T (3-term split) ----
        float S[8][4];
#pragma unroll
        for (int t = 0; t < 8; t++)
#pragma unroll
            for (int j = 0; j < 4; j++) S[t][j] = 0.f;

#pragma unroll
        for (int ks = 0; ks < 4; ks++) {
            const int bc2 = (ks * 16 + (((lid >> 3) & 1) << 3)) * 2;
            const int br  = (lid & 7) + (((lid >> 4) & 1) << 3);
#pragma unroll
            for (int p = 0; p < 4; p++) {
                uint32_t kh[4], kl[4];
                const uint32_t boff = (p * 16 + br) * SROW + bc2;
                ldm_x4(kh, bKh + boff);
                ldm_x4(kl, bKl + boff);
                mma_bf16(S[2 * p],     QH[ks], kh[0], kh[1]);
                mma_bf16(S[2 * p + 1], QH[ks], kh[2], kh[3]);
                mma_bf16(S[2 * p],     QL[ks], kh[0], kh[1]);
                mma_bf16(S[2 * p + 1], QL[ks], kh[2], kh[3]);
                mma_bf16(S[2 * p],     QH[ks], kl[0], kl[1]);
                mma_bf16(S[2 * p + 1], QH[ks], kl[2], kl[3]);
            }
        }

        // ---- logits = 0.125 * S * R2[l,|l-s|], online softmax ----
        const int s0 = kt * 64;
        float mx0 = -INFINITY, mx1 = -INFINITY;
#pragma unroll
        for (int t = 0; t < 8; t++) {
            const int sc = s0 + t * 8 + c2i;
            int dA0 = lA - sc;     dA0 = (dA0 < 0) ? -dA0 : dA0;
            int dA1 = lA - sc - 1; dA1 = (dA1 < 0) ? -dA1 : dA1;
            int dB0 = lB - sc;     dB0 = (dB0 < 0) ? -dB0 : dB0;
            int dB1 = lB - sc - 1; dB1 = (dB1 < 0) ? -dB1 : dB1;
            S[t][0] = 0.125f * S[t][0] * RA[dA0];
            S[t][1] = 0.125f * S[t][1] * RA[dA1];
            S[t][2] = 0.125f * S[t][2] * RB[dB0];
            S[t][3] = 0.125f * S[t][3] * RB[dB1];
            mx0 = fmaxf(mx0, fmaxf(S[t][0], S[t][1]));
            mx1 = fmaxf(mx1, fmaxf(S[t][2], S[t][3]));
        }
        mx0 = fmaxf(mx0, __shfl_xor_sync(0xffffffffu, mx0, 1));
        mx0 = fmaxf(mx0, __shfl_xor_sync(0xffffffffu, mx0, 2));
        mx1 = fmaxf(mx1, __shfl_xor_sync(0xffffffffu, mx1, 1));
        mx1 = fmaxf(mx1, __shfl_xor_sync(0xffffffffu, mx1, 2));

        const float mn0 = fmaxf(m0f, mx0), mn1 = fmaxf(m1f, mx1);
        const float al0 = __expf(m0f - mn0), al1 = __expf(m1f - mn1);
        m0f = mn0; m1f = mn1;

        float sum0 = 0.f, sum1 = 0.f;
        uint32_t PH[4][4], PL[4][4];
#pragma unroll
        for (int q = 0; q < 4; q++) {
#pragma unroll
            for (int u = 0; u < 2; u++) {           // tiles 2q, 2q+1
                const int t = 2 * q + u;
                float e0 = __expf(S[t][0] - mn0);
                float e1 = __expf(S[t][1] - mn0);
                float e2 = __expf(S[t][2] - mn1);
                float e3 = __expf(S[t][3] - mn1);
                sum0 += e0 + e1;
                sum1 += e2 + e3;
                float h0 = bhi(e0), h1 = bhi(e1), h2 = bhi(e2), h3 = bhi(e3);
                PH[q][2 * u]     = pack_bf16(h0, h1);
                PH[q][2 * u + 1] = pack_bf16(h2, h3);
                PL[q][2 * u]     = pack_bf16(e0 - h0, e1 - h1);
                PL[q][2 * u + 1] = pack_bf16(e2 - h2, e3 - h3);
            }
        }
        sum0 += __shfl_xor_sync(0xffffffffu, sum0, 1);
        sum0 += __shfl_xor_sync(0xffffffffu, sum0, 2);
        sum1 += __shfl_xor_sync(0xffffffffu, sum1, 1);
        sum1 += __shfl_xor_sync(0xffffffffu, sum1, 2);
        r0f = r0f * al0 + sum0;
        r1f = r1f * al1 + sum1;

#pragma unroll
        for (int t = 0; t < 8; t++) {
            O[t][0] *= al0; O[t][1] *= al0;
            O[t][2] *= al1; O[t][3] *= al1;
        }

        // ---- O += P @ V (3-term split), V via ldmatrix.trans ----
#pragma unroll
        for (int q = 0; q < 4; q++) {
            const int vr = (q * 16 + (lid & 7) + (((lid >> 3) & 1) << 3)) * SROW;
#pragma unroll
            for (int p = 0; p < 4; p++) {
                uint32_t vh[4], vl[4];
                const uint32_t voff = vr + (p * 16 + (((lid >> 4) & 1) << 3)) * 2;
                ldm_x4_t(vh, bVh + voff);
                ldm_x4_t(vl, bVl + voff);
                mma_bf16(O[2 * p],     PH[q], vh[0], vh[1]);
                mma_bf16(O[2 * p + 1], PH[q], vh[2], vh[3]);
                mma_bf16(O[2 * p],     PL[q], vh[0], vh[1]);
                mma_bf16(O[2 * p + 1], PL[q], vh[2], vh[3]);
                mma_bf16(O[2 * p],     PH[q], vl[0], vl[1]);
                mma_bf16(O[2 * p + 1], PH[q], vl[2], vl[3]);
            }
        }
        __syncthreads();

        if (kt + 2 < 16) {
            const int t = kt + 2;
            issue_kv64(Bt,             Khg + (size_t)t * 64 * 512, tid);
            issue_kv64(Bt + KVMAT,     Klg + (size_t)t * 64 * 512, tid);
            issue_kv64(Bt + 2 * KVMAT, Vhg + (size_t)t * 64 * 512, tid);
            issue_kv64(Bt + 3 * KVMAT, Vlg + (size_t)t * 64 * 512, tid);
            CP_COMMIT();
        }
    }

    // ---- epilogue: out[b, l, h*64+d] = O / r ----
    const float inv0 = 1.f / r0f, inv1 = 1.f / r1f;
    float* __restrict__ oA = out + (size_t)(b * 1024 + lA) * 512 + h * 64;
    float* __restrict__ oB = out + (size_t)(b * 1024 + lB) * 512 + h * 64;
#pragma unroll
    for (int t = 0; t < 8; t++) {
        const int d = t * 8 + c2i;
        *(float2*)(oA + d) = make_float2(O[t][0] * inv0, O[t][1] * inv0);
        *(float2*)(oB + d) = make_float2(O[t][2] * inv1, O[t][3] * inv1);
    }
}

// ---------------------------------------------------------------------------

extern "C" void kernel_launch(void* const* d_in, const int* in_sizes, int n_in,
                              void* d_out, int out_size)
{
    (void)in_sizes; (void)n_in; (void)out_size;
    const float* x  = (const float*)d_in[0];
    const float* Wq = (const float*)d_in[1];
    const float* Wk = (const float*)d_in[2];
    const float* Wv = (const float*)d_in[3];
    const float* We = (const float*)d_in[4];
    float* out = (float*)d_out;

    const int SMEM_MMA = 2 * BUF;   // 81920
    cudaFuncSetAttribute(k_mma_qkv, cudaFuncAttributeMaxDynamicSharedMemorySize, SMEM_MMA);
    cudaFuncSetAttribute(k_mma_rel, cudaFuncAttributeMaxDynamicSharedMemorySize, SMEM_MMA);
    cudaFuncSetAttribute(k_attn_mma, cudaFuncAttributeMaxDynamicSharedMemorySize, SMEM_ATT);

    k_split_x<<<4096, 256>>>(x);
    k_wsplit<<<dim3(16, 16, 3), dim3(32, 8)>>>(Wq, Wk, Wv);
    k_wesplit<<<256, 256>>>(We);
    k_mma_qkv<<<dim3(4, 64, 3), 256, SMEM_MMA>>>();
    k_mma_rel<<<dim3(8, 8, 64), 256, SMEM_MMA>>>();
    k_attn_mma<<<dim3(8, 8, 8), 256, SMEM_ATT>>>(out);
}